// round 1
// baseline (speedup 1.0000x reference)
#include <cuda_runtime.h>
#include <math.h>

#define NN 100000
#define NE 1600000
#define NG 512

// ---------------- device scratch (static globals; no allocation) ----------------
__device__ float g_agg[NN * 128];        // aggregation buffer (layer0 uses 128, rest 64)
__device__ float g_t[NN * 64];           // GEMM1 output (pre-BN)
__device__ float g_h0[NN * 64];          // ping-pong layer outputs
__device__ float g_h1[NN * 64];
__device__ float g_stats[128];           // [0:64) sum, [64:128) sumsq
__device__ float g_scale[64];
__device__ float g_shift[64];
__device__ float g_pooled[NG * 256];     // pooled hcat
__device__ float g_head1[NG * 64];       // head GEMM1 output

// ---------------- zero kernels ----------------
__global__ void zero_agg_kernel(int n4) {
    int i = blockIdx.x * blockDim.x + threadIdx.x;
    if (i < n4) ((float4*)g_agg)[i] = make_float4(0.f, 0.f, 0.f, 0.f);
}
__global__ void zero_stats_kernel() { g_stats[threadIdx.x] = 0.f; }   // <<<1,128>>>
__global__ void zero_pooled_kernel() {                                 // <<<512,256>>>
    int i = blockIdx.x * blockDim.x + threadIdx.x;
    g_pooled[i] = 0.f;
}

// ---------------- edge scatter: agg[dst] += X[src] ----------------
template<int F4, int SH>
__global__ void __launch_bounds__(256) scatter_kernel(
    const int* __restrict__ ei, int E, const float* __restrict__ xin, int xsel)
{
    unsigned tid = blockIdx.x * 256u + threadIdx.x;
    if (tid >= (unsigned)E * (unsigned)F4) return;
    int e  = (int)(tid >> SH);
    int ch = (int)(tid & (F4 - 1));
    const float* X = (xsel == 0) ? xin : (xsel == 1 ? g_h0 : g_h1);
    int src = __ldg(&ei[e]);
    int dst = __ldg(&ei[E + e]);
    float4 v = ((const float4*)X)[src * F4 + ch];
    atomicAdd(((float4*)g_agg) + dst * F4 + ch, v);   // RED.128, sm_90+
}

// ---------------- GEMM1: t = ((1+eps)*X + agg) @ W1 + b1 ----------------
// 32 nodes / block, 8 warps, each warp = 4 nodes x 64 channels (2 ch/lane).
template<int F>
__global__ void __launch_bounds__(256) gemm1_kernel(
    const float* __restrict__ xin, int xsel,
    const float* __restrict__ eps_arr, int layer,
    const float* __restrict__ W, const float* __restrict__ B, int N)
{
    __shared__ float xs[32 * F];
    __shared__ float ws[F * 64];
    const float* X = (xsel == 0) ? xin : (xsel == 1 ? g_h0 : g_h1);
    int tid = threadIdx.x;

    const float4* Wv = (const float4*)W;
    float4* wsv = (float4*)ws;
    #pragma unroll
    for (int i = tid; i < F * 16; i += 256) wsv[i] = Wv[i];

    float oe = 1.0f + __ldg(&eps_arr[layer]);
    int base = blockIdx.x * 32;
    const float4* Xv = (const float4*)X;
    const float4* Av = (const float4*)g_agg;
    float4* xsv = (float4*)xs;
    constexpr int C = F / 4;
    for (int i = tid; i < 32 * C; i += 256) {
        int r = i / C;
        int row = base + r;
        float4 v = make_float4(0.f, 0.f, 0.f, 0.f);
        if (row < N) {
            int gi = row * C + (i - r * C);
            float4 xv = Xv[gi]; float4 av = Av[gi];
            v.x = fmaf(oe, xv.x, av.x);
            v.y = fmaf(oe, xv.y, av.y);
            v.z = fmaf(oe, xv.z, av.z);
            v.w = fmaf(oe, xv.w, av.w);
        }
        xsv[i] = v;
    }
    __syncthreads();

    int w = tid >> 5, lane = tid & 31;
    int c = lane << 1;
    float2 bb = *(const float2*)&B[c];
    float acc0[4], acc1[4];
    #pragma unroll
    for (int r = 0; r < 4; r++) { acc0[r] = bb.x; acc1[r] = bb.y; }
    const float* xrow = &xs[(w * 4) * F];
    #pragma unroll 2
    for (int k = 0; k < F; k++) {
        float2 wv = *(const float2*)&ws[k * 64 + c];
        #pragma unroll
        for (int r = 0; r < 4; r++) {
            float xv = xrow[r * F + k];
            acc0[r] = fmaf(xv, wv.x, acc0[r]);
            acc1[r] = fmaf(xv, wv.y, acc1[r]);
        }
    }
    #pragma unroll
    for (int r = 0; r < 4; r++) {
        int row = base + w * 4 + r;
        if (row < N) *(float2*)&g_t[row * 64 + c] = make_float2(acc0[r], acc1[r]);
    }
}

// ---------------- node BN stats: per-channel sum / sumsq over g_t ----------------
__global__ void __launch_bounds__(256) bn_stats_kernel(int N)
{
    __shared__ float ssum[64], ssq[64];
    int tid = threadIdx.x;
    if (tid < 64) { ssum[tid] = 0.f; ssq[tid] = 0.f; }
    __syncthreads();
    int c = tid & 63;
    int r0 = (blockIdx.x * 256 + tid) >> 6;
    int stride = (gridDim.x * 256) >> 6;
    float s = 0.f, q = 0.f;
    for (int r = r0; r < N; r += stride) {
        float v = g_t[r * 64 + c];
        s += v; q = fmaf(v, v, q);
    }
    atomicAdd(&ssum[c], s);
    atomicAdd(&ssq[c], q);
    __syncthreads();
    if (tid < 64) {
        atomicAdd(&g_stats[tid], ssum[tid]);
        atomicAdd(&g_stats[64 + tid], ssq[tid]);
    }
}

__global__ void bn_finalize_kernel(const float* __restrict__ g,
                                   const float* __restrict__ be, float ninv)
{
    int c = threadIdx.x;  // 64 threads
    float mean = g_stats[c] * ninv;
    float var  = g_stats[64 + c] * ninv - mean * mean;
    float s = g[c] * rsqrtf(var + 1e-5f);
    g_scale[c] = s;
    g_shift[c] = fmaf(-mean, s, be[c]);
}

// ---------------- GEMM2: h = relu(relu(bn(t)) @ W2 + b2), fused segment-sum pool ----------------
__global__ void __launch_bounds__(256) gemm2_kernel(
    const float* __restrict__ W, const float* __restrict__ B,
    int outsel, const int* __restrict__ batch, int pool_off, int N)
{
    __shared__ float xs[32 * 64];
    __shared__ float ws[64 * 64];
    float* H = (outsel == 1) ? g_h0 : g_h1;
    int tid = threadIdx.x;

    const float4* Wv = (const float4*)W;
    float4* wsv = (float4*)ws;
    #pragma unroll
    for (int i = tid; i < 1024; i += 256) wsv[i] = Wv[i];

    int base = blockIdx.x * 32;
    const float4* Tv = (const float4*)g_t;
    float4* xsv = (float4*)xs;
    for (int i = tid; i < 32 * 16; i += 256) {
        int r = i >> 4; int ch = i & 15; int row = base + r;
        float4 v = make_float4(0.f, 0.f, 0.f, 0.f);
        if (row < N) {
            float4 t = Tv[row * 16 + ch];
            int cb = ch * 4;
            v.x = fmaxf(fmaf(t.x, g_scale[cb + 0], g_shift[cb + 0]), 0.f);
            v.y = fmaxf(fmaf(t.y, g_scale[cb + 1], g_shift[cb + 1]), 0.f);
            v.z = fmaxf(fmaf(t.z, g_scale[cb + 2], g_shift[cb + 2]), 0.f);
            v.w = fmaxf(fmaf(t.w, g_scale[cb + 3], g_shift[cb + 3]), 0.f);
        }
        xsv[i] = v;
    }
    __syncthreads();

    int w = tid >> 5, lane = tid & 31;
    int c = lane << 1;
    float2 bb = *(const float2*)&B[c];
    float acc0[4], acc1[4];
    #pragma unroll
    for (int r = 0; r < 4; r++) { acc0[r] = bb.x; acc1[r] = bb.y; }
    const float* xrow = &xs[(w * 4) * 64];
    #pragma unroll 2
    for (int k = 0; k < 64; k++) {
        float2 wv = *(const float2*)&ws[k * 64 + c];
        #pragma unroll
        for (int r = 0; r < 4; r++) {
            float xv = xrow[r * 64 + k];
            acc0[r] = fmaf(xv, wv.x, acc0[r]);
            acc1[r] = fmaf(xv, wv.y, acc1[r]);
        }
    }

    // epilogue: relu, store H, pool into g_pooled (batch is sorted -> run-compress atomics)
    int bprev = -1; float p0 = 0.f, p1 = 0.f;
    #pragma unroll
    for (int r = 0; r < 4; r++) {
        int row = base + w * 4 + r;
        if (row < N) {
            float o0 = fmaxf(acc0[r], 0.f), o1 = fmaxf(acc1[r], 0.f);
            *(float2*)&H[row * 64 + c] = make_float2(o0, o1);
            int bg = batch[row];
            if (bg != bprev) {
                if (bprev >= 0)
                    atomicAdd((float2*)&g_pooled[bprev * 256 + pool_off + c], make_float2(p0, p1));
                bprev = bg; p0 = 0.f; p1 = 0.f;
            }
            p0 += o0; p1 += o1;
        }
    }
    if (bprev >= 0)
        atomicAdd((float2*)&g_pooled[bprev * 256 + pool_off + c], make_float2(p0, p1));
}

// ---------------- head: out1 = pooled @ lin1_W + lin1_b ----------------
__global__ void head1_kernel(const float* __restrict__ W, const float* __restrict__ B)
{
    int gph = blockIdx.x, c = threadIdx.x;   // <<<512,64>>>
    __shared__ float xs[256];
    #pragma unroll
    for (int i = c; i < 256; i += 64) xs[i] = g_pooled[gph * 256 + i];
    __syncthreads();
    float a = B[c];
    #pragma unroll 4
    for (int k = 0; k < 256; k++) a = fmaf(xs[k], __ldg(&W[k * 64 + c]), a);
    g_head1[gph * 64 + c] = a;
}

// exact two-pass BN over the 512 graphs (cancellation-safe)
__global__ void head_bn_kernel(const float* __restrict__ g, const float* __restrict__ be)
{
    int c = blockIdx.x; int t = threadIdx.x;  // <<<64,256>>>
    __shared__ float red[256];
    float v0 = g_head1[t * 64 + c];
    float v1 = g_head1[(t + 256) * 64 + c];
    red[t] = v0 + v1;
    __syncthreads();
    for (int o = 128; o > 0; o >>= 1) { if (t < o) red[t] += red[t + o]; __syncthreads(); }
    float mean = red[0] * (1.0f / 512.0f);
    __syncthreads();
    float d0 = v0 - mean, d1 = v1 - mean;
    red[t] = d0 * d0 + d1 * d1;
    __syncthreads();
    for (int o = 128; o > 0; o >>= 1) { if (t < o) red[t] += red[t + o]; __syncthreads(); }
    if (t == 0) {
        float var = red[0] * (1.0f / 512.0f);
        float s = g[c] * rsqrtf(var + 1e-5f);
        g_scale[c] = s;
        g_shift[c] = fmaf(-mean, s, be[c]);
    }
}

// ---------------- head final: relu(bn) @ lin2 + b, log_softmax ----------------
__global__ void head_final_kernel(const float* __restrict__ W, const float* __restrict__ B,
                                  float* __restrict__ out)
{
    int gph = blockIdx.x; int c = threadIdx.x;   // <<<512,64>>>
    __shared__ float hn[64];
    __shared__ float logits[10];
    hn[c] = fmaxf(fmaf(g_head1[gph * 64 + c], g_scale[c], g_shift[c]), 0.f);
    __syncthreads();
    if (c < 10) {
        float a = B[c];
        #pragma unroll
        for (int k = 0; k < 64; k++) a = fmaf(hn[k], W[k * 10 + c], a);
        logits[c] = a;
    }
    __syncthreads();
    if (c == 0) {
        float m = logits[0];
        #pragma unroll
        for (int j = 1; j < 10; j++) m = fmaxf(m, logits[j]);
        float ssum = 0.f;
        #pragma unroll
        for (int j = 0; j < 10; j++) ssum += expf(logits[j] - m);
        float lse = m + logf(ssum);
        #pragma unroll
        for (int j = 0; j < 10; j++) out[gph * 10 + j] = logits[j] - lse;
    }
}

// ---------------- launch ----------------
extern "C" void kernel_launch(void* const* d_in, const int* in_sizes, int n_in,
                              void* d_out, int out_size)
{
    const float* x     = (const float*)d_in[0];
    const int*   ei    = (const int*)d_in[1];
    const int*   batch = (const int*)d_in[2];
    const float* eps   = (const float*)d_in[3];
    const int N = NN, E = NE;

    zero_pooled_kernel<<<512, 256>>>();

    for (int l = 0; l < 4; l++) {
        const float *W1, *b1, *gg, *be, *W2, *b2;
        if (l == 0) {
            W1 = (const float*)d_in[4]; b1 = (const float*)d_in[5];
            gg = (const float*)d_in[6]; be = (const float*)d_in[7];
            W2 = (const float*)d_in[8]; b2 = (const float*)d_in[9];
        } else {
            int j = l - 1;
            W1 = (const float*)d_in[10] + j * 64 * 64; b1 = (const float*)d_in[11] + j * 64;
            gg = (const float*)d_in[12] + j * 64;      be = (const float*)d_in[13] + j * 64;
            W2 = (const float*)d_in[14] + j * 64 * 64; b2 = (const float*)d_in[15] + j * 64;
        }
        int xsel   = (l == 0) ? 0 : ((((l - 1) & 1) == 0) ? 1 : 2);
        int outsel = ((l & 1) == 0) ? 1 : 2;
        int F4 = (l == 0) ? 32 : 16;
        int n4 = N * F4;

        zero_agg_kernel<<<(n4 + 255) / 256, 256>>>(n4);
        if (l == 0)
            scatter_kernel<32, 5><<<(E * 32 + 255) / 256, 256>>>(ei, E, x, xsel);
        else
            scatter_kernel<16, 4><<<(E * 16 + 255) / 256, 256>>>(ei, E, x, xsel);
        zero_stats_kernel<<<1, 128>>>();
        if (l == 0)
            gemm1_kernel<128><<<(N + 31) / 32, 256>>>(x, xsel, eps, l, W1, b1, N);
        else
            gemm1_kernel<64><<<(N + 31) / 32, 256>>>(x, xsel, eps, l, W1, b1, N);
        bn_stats_kernel<<<512, 256>>>(N);
        bn_finalize_kernel<<<1, 64>>>(gg, be, 1.0f / (float)N);
        gemm2_kernel<<<(N + 31) / 32, 256>>>(W2, b2, outsel, batch, l * 64, N);
    }

    head1_kernel<<<NG, 64>>>((const float*)d_in[16], (const float*)d_in[17]);
    head_bn_kernel<<<64, 256>>>((const float*)d_in[18], (const float*)d_in[19]);
    head_final_kernel<<<NG, 64>>>((const float*)d_in[20], (const float*)d_in[21], (float*)d_out);
}

// round 2
// speedup vs baseline: 1.4280x; 1.4280x over previous
#include <cuda_runtime.h>
#include <math.h>

#define NN 100000
#define NE 1600000
#define NG 512
#define NSB 98   // scan blocks of 1024 -> covers 100352 >= NN

// ---------------- device scratch ----------------
__device__ float g_agg[NN * 128];
__device__ float g_t[NN * 64];
__device__ float g_h0[NN * 64];
__device__ float g_h1[NN * 64];
__device__ float g_stats[128];     // zero at entry; bn_finalize re-zeroes after use
__device__ float g_scale[64];
__device__ float g_shift[64];
__device__ float g_pooled[NG * 256];
__device__ float g_head1[NG * 64];
__device__ int   g_deg[NN];
__device__ int   g_off[NN + 1];
__device__ int   g_cursor[NN];
__device__ int   g_srcs[NE];
__device__ int   g_bsum[NSB];
__device__ int   g_boff[NSB];

// ---------------- f32x2 helpers (FFMA2 path) ----------------
__device__ __forceinline__ unsigned long long f32x2_dup(float x) {
    unsigned long long r;
    asm("mov.b64 %0, {%1, %1};" : "=l"(r) : "f"(x));
    return r;
}
__device__ __forceinline__ void f32x2_fma(unsigned long long &d,
                                          unsigned long long a, unsigned long long b) {
    asm("fma.rn.f32x2 %0, %1, %2, %0;" : "+l"(d) : "l"(a), "l"(b));
}
__device__ __forceinline__ float2 f32x2_unpack(unsigned long long v) {
    float2 r;
    asm("mov.b64 {%0, %1}, %2;" : "=f"(r.x), "=f"(r.y) : "l"(v));
    return r;
}

// ---------------- small zero kernels ----------------
__global__ void zero_pooled_kernel() {
    int i = blockIdx.x * blockDim.x + threadIdx.x;
    g_pooled[i] = 0.f;
}
__global__ void zero_deg_kernel() {
    int i = blockIdx.x * 256 + threadIdx.x;
    if (i < NN) g_deg[i] = 0;
}

// ---------------- CSR build ----------------
__global__ void hist_kernel(const int* __restrict__ ei) {
    int e = blockIdx.x * 256 + threadIdx.x;
    if (e < NE) atomicAdd(&g_deg[ei[NE + e]], 1);
}
__global__ void scan1_kernel() {                  // <<<NSB,1024>>>
    __shared__ int s[1024];
    int tid = threadIdx.x;
    int i = blockIdx.x * 1024 + tid;
    int v = (i < NN) ? g_deg[i] : 0;
    s[tid] = v; __syncthreads();
    for (int off = 1; off < 1024; off <<= 1) {
        int t = (tid >= off) ? s[tid - off] : 0;
        __syncthreads();
        s[tid] += t;
        __syncthreads();
    }
    if (i < NN) g_off[i] = s[tid] - v;            // exclusive within block
    if (tid == 1023) g_bsum[blockIdx.x] = s[1023];
}
__global__ void scan2_kernel() {                  // <<<1,128>>>
    __shared__ int s[128];
    int tid = threadIdx.x;
    int v = (tid < NSB) ? g_bsum[tid] : 0;
    s[tid] = v; __syncthreads();
    for (int off = 1; off < 128; off <<= 1) {
        int t = (tid >= off) ? s[tid - off] : 0;
        __syncthreads();
        s[tid] += t;
        __syncthreads();
    }
    if (tid < NSB) g_boff[tid] = s[tid] - v;      // exclusive
}
__global__ void scan3_kernel() {                  // <<<NSB,1024>>>
    int i = blockIdx.x * 1024 + threadIdx.x;
    if (i < NN) {
        int v = g_off[i] + g_boff[blockIdx.x];
        g_off[i] = v;
        g_cursor[i] = v;
    }
    if (i == 0) g_off[NN] = NE;
}
__global__ void csr_scatter_kernel(const int* __restrict__ ei) {
    int e = blockIdx.x * 256 + threadIdx.x;
    if (e < NE) {
        int s = ei[e];
        int d = ei[NE + e];
        int p = atomicAdd(&g_cursor[d], 1);
        g_srcs[p] = s;
    }
}

// ---------------- gather aggregation: g_agg[n] = (1+eps)*X[n] + sum_{s in N(n)} X[s] ----------------
template<int F>
__global__ void __launch_bounds__(256) aggregate_kernel(
    const float* __restrict__ xin, int xsel,
    const float* __restrict__ eps_arr, int layer)
{
    int warp = (blockIdx.x * 256 + threadIdx.x) >> 5;
    int lane = threadIdx.x & 31;
    if (warp >= NN) return;
    const float* X = (xsel == 0) ? xin : (xsel == 1 ? g_h0 : g_h1);
    float oe = 1.0f + __ldg(&eps_arr[layer]);
    int beg = g_off[warp], end = g_off[warp + 1];

    if (F == 128) {
        const float4* X4 = (const float4*)X;
        float4 acc = X4[warp * 32 + lane];
        acc.x *= oe; acc.y *= oe; acc.z *= oe; acc.w *= oe;
        for (int bse = beg; bse < end; bse += 32) {
            int m = end - bse; if (m > 32) m = 32;
            int idx = (lane < m) ? g_srcs[bse + lane] : 0;
            int t = 0;
            for (; t + 4 <= m; t += 4) {
                int s0 = __shfl_sync(0xffffffffu, idx, t);
                int s1 = __shfl_sync(0xffffffffu, idx, t + 1);
                int s2 = __shfl_sync(0xffffffffu, idx, t + 2);
                int s3 = __shfl_sync(0xffffffffu, idx, t + 3);
                float4 a = X4[s0 * 32 + lane], b = X4[s1 * 32 + lane];
                float4 cc = X4[s2 * 32 + lane], d = X4[s3 * 32 + lane];
                acc.x += (a.x + b.x) + (cc.x + d.x);
                acc.y += (a.y + b.y) + (cc.y + d.y);
                acc.z += (a.z + b.z) + (cc.z + d.z);
                acc.w += (a.w + b.w) + (cc.w + d.w);
            }
            for (; t < m; t++) {
                int s0 = __shfl_sync(0xffffffffu, idx, t);
                float4 a = X4[s0 * 32 + lane];
                acc.x += a.x; acc.y += a.y; acc.z += a.z; acc.w += a.w;
            }
        }
        ((float4*)g_agg)[warp * 32 + lane] = acc;
    } else {
        const float2* X2 = (const float2*)X;
        float2 acc = X2[warp * 32 + lane];
        acc.x *= oe; acc.y *= oe;
        for (int bse = beg; bse < end; bse += 32) {
            int m = end - bse; if (m > 32) m = 32;
            int idx = (lane < m) ? g_srcs[bse + lane] : 0;
            int t = 0;
            for (; t + 4 <= m; t += 4) {
                int s0 = __shfl_sync(0xffffffffu, idx, t);
                int s1 = __shfl_sync(0xffffffffu, idx, t + 1);
                int s2 = __shfl_sync(0xffffffffu, idx, t + 2);
                int s3 = __shfl_sync(0xffffffffu, idx, t + 3);
                float2 a = X2[s0 * 32 + lane], b = X2[s1 * 32 + lane];
                float2 cc = X2[s2 * 32 + lane], d = X2[s3 * 32 + lane];
                acc.x += (a.x + b.x) + (cc.x + d.x);
                acc.y += (a.y + b.y) + (cc.y + d.y);
            }
            for (; t < m; t++) {
                int s0 = __shfl_sync(0xffffffffu, idx, t);
                float2 a = X2[s0 * 32 + lane];
                acc.x += a.x; acc.y += a.y;
            }
        }
        ((float2*)g_agg)[warp * 32 + lane] = acc;
    }
}

// ---------------- GEMM1 (f32x2): t = g_agg @ W1 + b1, fused BN stats ----------------
// block = 32 nodes x 64 ch; warp = 4 nodes (packed pairs) x 64 ch (2/lane)
template<int F>
__global__ void __launch_bounds__(256) gemm1_kernel(
    const float* __restrict__ W, const float* __restrict__ B, int N)
{
    constexpr int C = F / 4;
    __shared__ float xs[F * 34];     // transposed [k][node], stride 34 (8B-aligned pairs)
    __shared__ float ws[F * 64];
    __shared__ float ssum[64], ssq[64];
    int tid = threadIdx.x;

    const float4* Wv = (const float4*)W;
    float4* wsv = (float4*)ws;
    #pragma unroll
    for (int i = tid; i < F * 16; i += 256) wsv[i] = Wv[i];
    if (tid < 64) { ssum[tid] = 0.f; ssq[tid] = 0.f; }

    int base = blockIdx.x * 32;
    int n = tid & 31, kq = tid >> 5;
    int row = base + n;
    const float4* Av = (const float4*)g_agg;
    #pragma unroll
    for (int q = kq; q < C; q += 8) {
        float4 v = make_float4(0.f, 0.f, 0.f, 0.f);
        if (row < N) v = Av[row * C + q];
        xs[(4 * q + 0) * 34 + n] = v.x;
        xs[(4 * q + 1) * 34 + n] = v.y;
        xs[(4 * q + 2) * 34 + n] = v.z;
        xs[(4 * q + 3) * 34 + n] = v.w;
    }
    __syncthreads();

    int w4 = (tid >> 5) * 4;
    int c = (tid & 31) * 2;
    float2 bb = *(const float2*)&B[c];
    unsigned long long a00 = f32x2_dup(bb.x), a01 = f32x2_dup(bb.y);
    unsigned long long a10 = a00, a11 = a01;
    #pragma unroll 4
    for (int k = 0; k < F; k++) {
        unsigned long long xp01 = *(const unsigned long long*)&xs[k * 34 + w4];
        unsigned long long xp23 = *(const unsigned long long*)&xs[k * 34 + w4 + 2];
        float2 wv = *(const float2*)&ws[k * 64 + c];
        unsigned long long wx = f32x2_dup(wv.x), wy = f32x2_dup(wv.y);
        f32x2_fma(a00, xp01, wx); f32x2_fma(a01, xp01, wy);
        f32x2_fma(a10, xp23, wx); f32x2_fma(a11, xp23, wy);
    }
    float2 v00 = f32x2_unpack(a00), v01 = f32x2_unpack(a01);
    float2 v10 = f32x2_unpack(a10), v11 = f32x2_unpack(a11);
    float vals[4][2] = {{v00.x, v01.x}, {v00.y, v01.y}, {v10.x, v11.x}, {v10.y, v11.y}};

    float s0 = 0.f, s1 = 0.f, q0 = 0.f, q1 = 0.f;
    int rbase = base + w4;
    #pragma unroll
    for (int j = 0; j < 4; j++) {
        int r = rbase + j;
        if (r < N) {
            float x0 = vals[j][0], x1 = vals[j][1];
            *(float2*)&g_t[r * 64 + c] = make_float2(x0, x1);
            s0 += x0; s1 += x1;
            q0 = fmaf(x0, x0, q0); q1 = fmaf(x1, x1, q1);
        }
    }
    atomicAdd(&ssum[c], s0);  atomicAdd(&ssum[c + 1], s1);
    atomicAdd(&ssq[c], q0);   atomicAdd(&ssq[c + 1], q1);
    __syncthreads();
    if (tid < 64) {
        atomicAdd(&g_stats[tid], ssum[tid]);
        atomicAdd(&g_stats[64 + tid], ssq[tid]);
    }
}

__global__ void bn_finalize_kernel(const float* __restrict__ g,
                                   const float* __restrict__ be, float ninv)
{
    int c = threadIdx.x;  // 64 threads
    float mean = g_stats[c] * ninv;
    float var  = g_stats[64 + c] * ninv - mean * mean;
    g_stats[c] = 0.f; g_stats[64 + c] = 0.f;   // re-arm for next layer / next replay
    float s = g[c] * rsqrtf(var + 1e-5f);
    g_scale[c] = s;
    g_shift[c] = fmaf(-mean, s, be[c]);
}

// ---------------- GEMM2 (f32x2): h = relu(relu(bn(t)) @ W2 + b2), fused pooling ----------------
__global__ void __launch_bounds__(256) gemm2_kernel(
    const float* __restrict__ W, const float* __restrict__ B,
    int outsel, const int* __restrict__ batch, int pool_off, int N)
{
    __shared__ float xs[64 * 34];
    __shared__ float ws[64 * 64];
    float* H = (outsel == 1) ? g_h0 : g_h1;
    int tid = threadIdx.x;

    const float4* Wv = (const float4*)W;
    float4* wsv = (float4*)ws;
    #pragma unroll
    for (int i = tid; i < 1024; i += 256) wsv[i] = Wv[i];

    int base = blockIdx.x * 32;
    int n = tid & 31, kq = tid >> 5;
    int row = base + n;
    const float4* Tv = (const float4*)g_t;
    #pragma unroll
    for (int q = kq; q < 16; q += 8) {
        float4 v = make_float4(0.f, 0.f, 0.f, 0.f);
        if (row < N) {
            float4 t = Tv[row * 16 + q];
            int cb = q * 4;
            v.x = fmaxf(fmaf(t.x, g_scale[cb + 0], g_shift[cb + 0]), 0.f);
            v.y = fmaxf(fmaf(t.y, g_scale[cb + 1], g_shift[cb + 1]), 0.f);
            v.z = fmaxf(fmaf(t.z, g_scale[cb + 2], g_shift[cb + 2]), 0.f);
            v.w = fmaxf(fmaf(t.w, g_scale[cb + 3], g_shift[cb + 3]), 0.f);
        }
        xs[(4 * q + 0) * 34 + n] = v.x;
        xs[(4 * q + 1) * 34 + n] = v.y;
        xs[(4 * q + 2) * 34 + n] = v.z;
        xs[(4 * q + 3) * 34 + n] = v.w;
    }
    __syncthreads();

    int w4 = (tid >> 5) * 4;
    int c = (tid & 31) * 2;
    float2 bb = *(const float2*)&B[c];
    unsigned long long a00 = f32x2_dup(bb.x), a01 = f32x2_dup(bb.y);
    unsigned long long a10 = a00, a11 = a01;
    #pragma unroll 4
    for (int k = 0; k < 64; k++) {
        unsigned long long xp01 = *(const unsigned long long*)&xs[k * 34 + w4];
        unsigned long long xp23 = *(const unsigned long long*)&xs[k * 34 + w4 + 2];
        float2 wv = *(const float2*)&ws[k * 64 + c];
        unsigned long long wx = f32x2_dup(wv.x), wy = f32x2_dup(wv.y);
        f32x2_fma(a00, xp01, wx); f32x2_fma(a01, xp01, wy);
        f32x2_fma(a10, xp23, wx); f32x2_fma(a11, xp23, wy);
    }
    float2 v00 = f32x2_unpack(a00), v01 = f32x2_unpack(a01);
    float2 v10 = f32x2_unpack(a10), v11 = f32x2_unpack(a11);
    float vals[4][2] = {{v00.x, v01.x}, {v00.y, v01.y}, {v10.x, v11.x}, {v10.y, v11.y}};

    // epilogue: relu, store H, pool (batch sorted -> run-compressed atomics)
    int rbase = base + w4;
    int bprev = -1; float p0 = 0.f, p1 = 0.f;
    #pragma unroll
    for (int j = 0; j < 4; j++) {
        int r = rbase + j;
        if (r < N) {
            float o0 = fmaxf(vals[j][0], 0.f), o1 = fmaxf(vals[j][1], 0.f);
            *(float2*)&H[r * 64 + c] = make_float2(o0, o1);
            int bg = batch[r];
            if (bg != bprev) {
                if (bprev >= 0)
                    atomicAdd((float2*)&g_pooled[bprev * 256 + pool_off + c], make_float2(p0, p1));
                bprev = bg; p0 = 0.f; p1 = 0.f;
            }
            p0 += o0; p1 += o1;
        }
    }
    if (bprev >= 0)
        atomicAdd((float2*)&g_pooled[bprev * 256 + pool_off + c], make_float2(p0, p1));
}

// ---------------- head ----------------
__global__ void head1_kernel(const float* __restrict__ W, const float* __restrict__ B)
{
    int gph = blockIdx.x, c = threadIdx.x;   // <<<512,64>>>
    __shared__ float xs[256];
    #pragma unroll
    for (int i = c; i < 256; i += 64) xs[i] = g_pooled[gph * 256 + i];
    __syncthreads();
    float a = B[c];
    #pragma unroll 4
    for (int k = 0; k < 256; k++) a = fmaf(xs[k], __ldg(&W[k * 64 + c]), a);
    g_head1[gph * 64 + c] = a;
}

__global__ void head_bn_kernel(const float* __restrict__ g, const float* __restrict__ be)
{
    int c = blockIdx.x; int t = threadIdx.x;  // <<<64,256>>>
    __shared__ float red[256];
    float v0 = g_head1[t * 64 + c];
    float v1 = g_head1[(t + 256) * 64 + c];
    red[t] = v0 + v1;
    __syncthreads();
    for (int o = 128; o > 0; o >>= 1) { if (t < o) red[t] += red[t + o]; __syncthreads(); }
    float mean = red[0] * (1.0f / 512.0f);
    __syncthreads();
    float d0 = v0 - mean, d1 = v1 - mean;
    red[t] = d0 * d0 + d1 * d1;
    __syncthreads();
    for (int o = 128; o > 0; o >>= 1) { if (t < o) red[t] += red[t + o]; __syncthreads(); }
    if (t == 0) {
        float var = red[0] * (1.0f / 512.0f);
        float s = g[c] * rsqrtf(var + 1e-5f);
        g_scale[c] = s;
        g_shift[c] = fmaf(-mean, s, be[c]);
    }
}

__global__ void head_final_kernel(const float* __restrict__ W, const float* __restrict__ B,
                                  float* __restrict__ out)
{
    int gph = blockIdx.x; int c = threadIdx.x;   // <<<512,64>>>
    __shared__ float hn[64];
    __shared__ float logits[10];
    hn[c] = fmaxf(fmaf(g_head1[gph * 64 + c], g_scale[c], g_shift[c]), 0.f);
    __syncthreads();
    if (c < 10) {
        float a = B[c];
        #pragma unroll
        for (int k = 0; k < 64; k++) a = fmaf(hn[k], W[k * 10 + c], a);
        logits[c] = a;
    }
    __syncthreads();
    if (c == 0) {
        float m = logits[0];
        #pragma unroll
        for (int j = 1; j < 10; j++) m = fmaxf(m, logits[j]);
        float ssum = 0.f;
        #pragma unroll
        for (int j = 0; j < 10; j++) ssum += expf(logits[j] - m);
        float lse = m + logf(ssum);
        #pragma unroll
        for (int j = 0; j < 10; j++) out[gph * 10 + j] = logits[j] - lse;
    }
}

// ---------------- launch ----------------
extern "C" void kernel_launch(void* const* d_in, const int* in_sizes, int n_in,
                              void* d_out, int out_size)
{
    const float* x     = (const float*)d_in[0];
    const int*   ei    = (const int*)d_in[1];
    const int*   batch = (const int*)d_in[2];
    const float* eps   = (const float*)d_in[3];

    zero_pooled_kernel<<<512, 256>>>();

    // CSR build (per call; graph-captured)
    zero_deg_kernel<<<(NN + 255) / 256, 256>>>();
    hist_kernel<<<(NE + 255) / 256, 256>>>(ei);
    scan1_kernel<<<NSB, 1024>>>();
    scan2_kernel<<<1, 128>>>();
    scan3_kernel<<<NSB, 1024>>>();
    csr_scatter_kernel<<<(NE + 255) / 256, 256>>>(ei);

    for (int l = 0; l < 4; l++) {
        const float *W1, *b1, *gg, *be, *W2, *b2;
        if (l == 0) {
            W1 = (const float*)d_in[4]; b1 = (const float*)d_in[5];
            gg = (const float*)d_in[6]; be = (const float*)d_in[7];
            W2 = (const float*)d_in[8]; b2 = (const float*)d_in[9];
        } else {
            int j = l - 1;
            W1 = (const float*)d_in[10] + j * 64 * 64; b1 = (const float*)d_in[11] + j * 64;
            gg = (const float*)d_in[12] + j * 64;      be = (const float*)d_in[13] + j * 64;
            W2 = (const float*)d_in[14] + j * 64 * 64; b2 = (const float*)d_in[15] + j * 64;
        }
        int xsel   = (l == 0) ? 0 : ((((l - 1) & 1) == 0) ? 1 : 2);
        int outsel = ((l & 1) == 0) ? 1 : 2;
        int nwarp_blocks = (NN * 32 + 255) / 256;

        if (l == 0) {
            aggregate_kernel<128><<<nwarp_blocks, 256>>>(x, xsel, eps, l);
            gemm1_kernel<128><<<(NN + 31) / 32, 256>>>(W1, b1, NN);
        } else {
            aggregate_kernel<64><<<nwarp_blocks, 256>>>(x, xsel, eps, l);
            gemm1_kernel<64><<<(NN + 31) / 32, 256>>>(W1, b1, NN);
        }
        bn_finalize_kernel<<<1, 64>>>(gg, be, 1.0f / (float)NN);
        gemm2_kernel<<<(NN + 31) / 32, 256>>>(W2, b2, outsel, batch, l * 64, NN);
    }

    head1_kernel<<<NG, 64>>>((const float*)d_in[16], (const float*)d_in[17]);
    head_bn_kernel<<<64, 256>>>((const float*)d_in[18], (const float*)d_in[19]);
    head_final_kernel<<<NG, 64>>>((const float*)d_in[20], (const float*)d_in[21], (float*)d_out);
}

// round 3
// speedup vs baseline: 1.4647x; 1.0257x over previous
#include <cuda_runtime.h>
#include <math.h>

#define NN 100000
#define NE 1600000
#define NG 512
#define NSB 98   // scan blocks of 1024 -> covers 100352 >= NN

// ---------------- device scratch ----------------
__device__ float g_y[NN * 64];     // y = X @ W1 (pre-aggregation)
__device__ float g_t[NN * 64];     // t = (1+eps)y + gather(y) + b1
__device__ float g_stats[128];     // zeroed by bn_finalize after each use
__device__ float g_scale[64];
__device__ float g_shift[64];
__device__ float g_pooled[NG * 256];
__device__ float g_head1[NG * 64];
__device__ int   g_deg[NN];
__device__ int   g_off[NN + 1];
__device__ int   g_cursor[NN];
__device__ int   g_srcs[NE];
__device__ int   g_bsum[NSB];
__device__ int   g_boff[NSB];

// ---------------- f32x2 helpers ----------------
__device__ __forceinline__ unsigned long long f32x2_dup(float x) {
    unsigned long long r;
    asm("mov.b64 %0, {%1, %1};" : "=l"(r) : "f"(x));
    return r;
}
__device__ __forceinline__ void f32x2_fma(unsigned long long &d,
                                          unsigned long long a, unsigned long long b) {
    asm("fma.rn.f32x2 %0, %1, %2, %0;" : "+l"(d) : "l"(a), "l"(b));
}
__device__ __forceinline__ float2 f32x2_unpack(unsigned long long v) {
    float2 r;
    asm("mov.b64 {%0, %1}, %2;" : "=f"(r.x), "=f"(r.y) : "l"(v));
    return r;
}

// ---------------- small kernels ----------------
__global__ void zero_pooled_kernel() {
    int i = blockIdx.x * blockDim.x + threadIdx.x;
    g_pooled[i] = 0.f;
}
__global__ void zero_deg_kernel() {
    int i = blockIdx.x * 256 + threadIdx.x;
    if (i < NN) g_deg[i] = 0;
}

// ---------------- CSR build ----------------
__global__ void hist_kernel(const int* __restrict__ ei) {
    int e = blockIdx.x * 256 + threadIdx.x;
    if (e < NE) atomicAdd(&g_deg[ei[NE + e]], 1);
}
__global__ void scan1_kernel() {                  // <<<NSB,1024>>>
    __shared__ int s[1024];
    int tid = threadIdx.x;
    int i = blockIdx.x * 1024 + tid;
    int v = (i < NN) ? g_deg[i] : 0;
    s[tid] = v; __syncthreads();
    for (int off = 1; off < 1024; off <<= 1) {
        int t = (tid >= off) ? s[tid - off] : 0;
        __syncthreads();
        s[tid] += t;
        __syncthreads();
    }
    if (i < NN) g_off[i] = s[tid] - v;
    if (tid == 1023) g_bsum[blockIdx.x] = s[1023];
}
__global__ void scan2_kernel() {                  // <<<1,128>>>
    __shared__ int s[128];
    int tid = threadIdx.x;
    int v = (tid < NSB) ? g_bsum[tid] : 0;
    s[tid] = v; __syncthreads();
    for (int off = 1; off < 128; off <<= 1) {
        int t = (tid >= off) ? s[tid - off] : 0;
        __syncthreads();
        s[tid] += t;
        __syncthreads();
    }
    if (tid < NSB) g_boff[tid] = s[tid] - v;
}
__global__ void scan3_kernel() {                  // <<<NSB,1024>>>
    int i = blockIdx.x * 1024 + threadIdx.x;
    if (i < NN) {
        int v = g_off[i] + g_boff[blockIdx.x];
        g_off[i] = v;
        g_cursor[i] = v;
    }
    if (i == 0) g_off[NN] = NE;
}
__global__ void csr_scatter_kernel(const int* __restrict__ ei) {
    int e = blockIdx.x * 256 + threadIdx.x;
    if (e < NE) {
        int s = ei[e];
        int d = ei[NE + e];
        int p = atomicAdd(&g_cursor[d], 1);
        g_srcs[p] = s;
    }
}

// ---------------- gemm_pre: y = X @ W1_0 (F=128 -> 64, no bias) ----------------
__global__ void __launch_bounds__(256) gemm_pre_kernel(
    const float* __restrict__ X, const float* __restrict__ W, int N)
{
    constexpr int F = 128;
    __shared__ float xs[F * 34];
    __shared__ float ws[F * 64];
    int tid = threadIdx.x;

    const float4* Wv = (const float4*)W;
    float4* wsv = (float4*)ws;
    #pragma unroll
    for (int i = tid; i < F * 16; i += 256) wsv[i] = Wv[i];

    int base = blockIdx.x * 32;
    int n = tid & 31, kq = tid >> 5;
    int row = base + n;
    const float4* Xv = (const float4*)X;
    #pragma unroll
    for (int q = kq; q < F / 4; q += 8) {
        float4 v = make_float4(0.f, 0.f, 0.f, 0.f);
        if (row < N) v = Xv[row * (F / 4) + q];
        xs[(4 * q + 0) * 34 + n] = v.x;
        xs[(4 * q + 1) * 34 + n] = v.y;
        xs[(4 * q + 2) * 34 + n] = v.z;
        xs[(4 * q + 3) * 34 + n] = v.w;
    }
    __syncthreads();

    int w4 = (tid >> 5) * 4;
    int c = (tid & 31) * 2;
    unsigned long long a00 = 0ull, a01 = 0ull, a10 = 0ull, a11 = 0ull;
    #pragma unroll 4
    for (int k = 0; k < F; k++) {
        unsigned long long xp01 = *(const unsigned long long*)&xs[k * 34 + w4];
        unsigned long long xp23 = *(const unsigned long long*)&xs[k * 34 + w4 + 2];
        float2 wv = *(const float2*)&ws[k * 64 + c];
        unsigned long long wx = f32x2_dup(wv.x), wy = f32x2_dup(wv.y);
        f32x2_fma(a00, xp01, wx); f32x2_fma(a01, xp01, wy);
        f32x2_fma(a10, xp23, wx); f32x2_fma(a11, xp23, wy);
    }
    float2 v00 = f32x2_unpack(a00), v01 = f32x2_unpack(a01);
    float2 v10 = f32x2_unpack(a10), v11 = f32x2_unpack(a11);
    float vals[4][2] = {{v00.x, v01.x}, {v00.y, v01.y}, {v10.x, v11.x}, {v10.y, v11.y}};
    #pragma unroll
    for (int j = 0; j < 4; j++) {
        int r = base + w4 + j;
        if (r < N) *(float2*)&g_y[r * 64 + c] = make_float2(vals[j][0], vals[j][1]);
    }
}

// ---------------- aggregate: t[n] = (1+eps)*y[n] + sum_nb y + b1; fused BN stats ----------------
__global__ void __launch_bounds__(256) aggregate_kernel(
    const float* __restrict__ eps_arr, int layer, const float* __restrict__ b1)
{
    __shared__ float ss[128];
    int tid = threadIdx.x;
    if (tid < 128) ss[tid] = 0.f;
    __syncthreads();

    int warp = (blockIdx.x * 256 + tid) >> 5;
    int lane = tid & 31;
    if (warp < NN) {
        float oe = 1.0f + __ldg(&eps_arr[layer]);
        int beg = g_off[warp], end = g_off[warp + 1];
        const float2* Y2 = (const float2*)g_y;
        float2 acc = Y2[warp * 32 + lane];
        acc.x *= oe; acc.y *= oe;
        for (int bse = beg; bse < end; bse += 32) {
            int m = end - bse; if (m > 32) m = 32;
            int idx = (lane < m) ? g_srcs[bse + lane] : 0;
            int t = 0;
            for (; t + 4 <= m; t += 4) {
                int s0 = __shfl_sync(0xffffffffu, idx, t);
                int s1 = __shfl_sync(0xffffffffu, idx, t + 1);
                int s2 = __shfl_sync(0xffffffffu, idx, t + 2);
                int s3 = __shfl_sync(0xffffffffu, idx, t + 3);
                float2 a = Y2[s0 * 32 + lane], b = Y2[s1 * 32 + lane];
                float2 cc = Y2[s2 * 32 + lane], d = Y2[s3 * 32 + lane];
                acc.x += (a.x + b.x) + (cc.x + d.x);
                acc.y += (a.y + b.y) + (cc.y + d.y);
            }
            for (; t < m; t++) {
                int s0 = __shfl_sync(0xffffffffu, idx, t);
                float2 a = Y2[s0 * 32 + lane];
                acc.x += a.x; acc.y += a.y;
            }
        }
        float2 bb = *(const float2*)&b1[2 * lane];
        acc.x += bb.x; acc.y += bb.y;
        *(float2*)&g_t[warp * 64 + 2 * lane] = acc;
        atomicAdd(&ss[2 * lane], acc.x);
        atomicAdd(&ss[2 * lane + 1], acc.y);
        atomicAdd(&ss[64 + 2 * lane], acc.x * acc.x);
        atomicAdd(&ss[64 + 2 * lane + 1], acc.y * acc.y);
    }
    __syncthreads();
    if (tid < 128) atomicAdd(&g_stats[tid], ss[tid]);
}

__global__ void bn_finalize_kernel(const float* __restrict__ g,
                                   const float* __restrict__ be, float ninv)
{
    int c = threadIdx.x;  // 64 threads
    float mean = g_stats[c] * ninv;
    float var  = g_stats[64 + c] * ninv - mean * mean;
    g_stats[c] = 0.f; g_stats[64 + c] = 0.f;   // re-arm
    float s = g[c] * rsqrtf(var + 1e-5f);
    g_scale[c] = s;
    g_shift[c] = fmaf(-mean, s, be[c]);
}

// ---------------- gemm_dual: z=relu(bn(t)); H=relu(z@W2+b2); pool H; y=H@W1n ----------------
// 64 nodes/block, 8 warps; warp = 8 nodes x 64 ch (2 ch/lane, node pairs packed f32x2)
__global__ void __launch_bounds__(256) gemm_dual_kernel(
    const float* __restrict__ W2, const float* __restrict__ B2,
    const int* __restrict__ batch, int pool_off,
    const float* __restrict__ W1n, int has_next, int N)
{
    __shared__ float xs[64 * 66];
    __shared__ float ws2s[64 * 64];
    __shared__ float ws1s[64 * 64];
    int tid = threadIdx.x;

    {
        const float4* Wv = (const float4*)W2;
        float4* dv = (float4*)ws2s;
        #pragma unroll
        for (int i = tid; i < 1024; i += 256) dv[i] = Wv[i];
    }
    if (has_next) {
        const float4* Wv = (const float4*)W1n;
        float4* dv = (float4*)ws1s;
        #pragma unroll
        for (int i = tid; i < 1024; i += 256) dv[i] = Wv[i];
    }

    int base = blockIdx.x * 64;
    int n = tid & 63, q0 = tid >> 6;     // q0 in 0..3
    int row = base + n;
    const float4* Tv = (const float4*)g_t;
    #pragma unroll
    for (int q = q0; q < 16; q += 4) {
        float4 v = make_float4(0.f, 0.f, 0.f, 0.f);
        if (row < N) {
            float4 t = Tv[row * 16 + q];
            int cb = q * 4;
            v.x = fmaxf(fmaf(t.x, g_scale[cb + 0], g_shift[cb + 0]), 0.f);
            v.y = fmaxf(fmaf(t.y, g_scale[cb + 1], g_shift[cb + 1]), 0.f);
            v.z = fmaxf(fmaf(t.z, g_scale[cb + 2], g_shift[cb + 2]), 0.f);
            v.w = fmaxf(fmaf(t.w, g_scale[cb + 3], g_shift[cb + 3]), 0.f);
        }
        xs[(4 * q + 0) * 66 + n] = v.x;
        xs[(4 * q + 1) * 66 + n] = v.y;
        xs[(4 * q + 2) * 66 + n] = v.z;
        xs[(4 * q + 3) * 66 + n] = v.w;
    }
    __syncthreads();

    int w8 = (tid >> 5) * 8;
    int c = (tid & 31) * 2;
    float2 bb = *(const float2*)&B2[c];
    unsigned long long acc[4][2];
    #pragma unroll
    for (int p = 0; p < 4; p++) { acc[p][0] = f32x2_dup(bb.x); acc[p][1] = f32x2_dup(bb.y); }
    #pragma unroll 4
    for (int k = 0; k < 64; k++) {
        float2 wv = *(const float2*)&ws2s[k * 64 + c];
        unsigned long long wx = f32x2_dup(wv.x), wy = f32x2_dup(wv.y);
        #pragma unroll
        for (int p = 0; p < 4; p++) {
            unsigned long long xp = *(const unsigned long long*)&xs[k * 66 + w8 + 2 * p];
            f32x2_fma(acc[p][0], xp, wx);
            f32x2_fma(acc[p][1], xp, wy);
        }
    }
    float H[8][2];
    #pragma unroll
    for (int p = 0; p < 4; p++) {
        float2 u0 = f32x2_unpack(acc[p][0]);   // {node 2p ch c, node 2p+1 ch c}
        float2 u1 = f32x2_unpack(acc[p][1]);   // {node 2p ch c+1, node 2p+1 ch c+1}
        H[2 * p + 0][0] = fmaxf(u0.x, 0.f); H[2 * p + 0][1] = fmaxf(u1.x, 0.f);
        H[2 * p + 1][0] = fmaxf(u0.y, 0.f); H[2 * p + 1][1] = fmaxf(u1.y, 0.f);
    }

    // pooling (batch sorted -> run-compressed atomics)
    int rbase = base + w8;
    int bprev = -1; float p0 = 0.f, p1 = 0.f;
    #pragma unroll
    for (int j = 0; j < 8; j++) {
        int r = rbase + j;
        if (r < N) {
            int bg = batch[r];
            if (bg != bprev) {
                if (bprev >= 0)
                    atomicAdd((float2*)&g_pooled[bprev * 256 + pool_off + c], make_float2(p0, p1));
                bprev = bg; p0 = 0.f; p1 = 0.f;
            }
            p0 += H[j][0]; p1 += H[j][1];
        }
    }
    if (bprev >= 0)
        atomicAdd((float2*)&g_pooled[bprev * 256 + pool_off + c], make_float2(p0, p1));

    if (has_next) {
        // store H into xs transposed (warp-private columns) and run second GEMM
        #pragma unroll
        for (int p = 0; p < 4; p++) {
            *(float2*)&xs[c * 66 + w8 + 2 * p]       = make_float2(H[2 * p][0], H[2 * p + 1][0]);
            *(float2*)&xs[(c + 1) * 66 + w8 + 2 * p] = make_float2(H[2 * p][1], H[2 * p + 1][1]);
        }
        __syncwarp();
        unsigned long long acc2[4][2];
        #pragma unroll
        for (int p = 0; p < 4; p++) { acc2[p][0] = 0ull; acc2[p][1] = 0ull; }
        #pragma unroll 4
        for (int k = 0; k < 64; k++) {
            float2 wv = *(const float2*)&ws1s[k * 64 + c];
            unsigned long long wx = f32x2_dup(wv.x), wy = f32x2_dup(wv.y);
            #pragma unroll
            for (int p = 0; p < 4; p++) {
                unsigned long long xp = *(const unsigned long long*)&xs[k * 66 + w8 + 2 * p];
                f32x2_fma(acc2[p][0], xp, wx);
                f32x2_fma(acc2[p][1], xp, wy);
            }
        }
        #pragma unroll
        for (int p = 0; p < 4; p++) {
            float2 u0 = f32x2_unpack(acc2[p][0]);
            float2 u1 = f32x2_unpack(acc2[p][1]);
            int r0 = rbase + 2 * p, r1 = r0 + 1;
            if (r0 < N) *(float2*)&g_y[r0 * 64 + c] = make_float2(u0.x, u1.x);
            if (r1 < N) *(float2*)&g_y[r1 * 64 + c] = make_float2(u0.y, u1.y);
        }
    }
}

// ---------------- head ----------------
__global__ void head1_kernel(const float* __restrict__ W, const float* __restrict__ B)
{
    int gph = blockIdx.x, c = threadIdx.x;   // <<<512,64>>>
    __shared__ float xs[256];
    #pragma unroll
    for (int i = c; i < 256; i += 64) xs[i] = g_pooled[gph * 256 + i];
    __syncthreads();
    float a = B[c];
    #pragma unroll 4
    for (int k = 0; k < 256; k++) a = fmaf(xs[k], __ldg(&W[k * 64 + c]), a);
    g_head1[gph * 64 + c] = a;
}

__global__ void head_bn_kernel(const float* __restrict__ g, const float* __restrict__ be)
{
    int c = blockIdx.x; int t = threadIdx.x;  // <<<64,256>>>
    __shared__ float red[256];
    float v0 = g_head1[t * 64 + c];
    float v1 = g_head1[(t + 256) * 64 + c];
    red[t] = v0 + v1;
    __syncthreads();
    for (int o = 128; o > 0; o >>= 1) { if (t < o) red[t] += red[t + o]; __syncthreads(); }
    float mean = red[0] * (1.0f / 512.0f);
    __syncthreads();
    float d0 = v0 - mean, d1 = v1 - mean;
    red[t] = d0 * d0 + d1 * d1;
    __syncthreads();
    for (int o = 128; o > 0; o >>= 1) { if (t < o) red[t] += red[t + o]; __syncthreads(); }
    if (t == 0) {
        float var = red[0] * (1.0f / 512.0f);
        float s = g[c] * rsqrtf(var + 1e-5f);
        g_scale[c] = s;
        g_shift[c] = fmaf(-mean, s, be[c]);
    }
}

__global__ void head_final_kernel(const float* __restrict__ W, const float* __restrict__ B,
                                  float* __restrict__ out)
{
    int gph = blockIdx.x; int c = threadIdx.x;   // <<<512,64>>>
    __shared__ float hn[64];
    __shared__ float logits[10];
    hn[c] = fmaxf(fmaf(g_head1[gph * 64 + c], g_scale[c], g_shift[c]), 0.f);
    __syncthreads();
    if (c < 10) {
        float a = B[c];
        #pragma unroll
        for (int k = 0; k < 64; k++) a = fmaf(hn[k], W[k * 10 + c], a);
        logits[c] = a;
    }
    __syncthreads();
    if (c == 0) {
        float m = logits[0];
        #pragma unroll
        for (int j = 1; j < 10; j++) m = fmaxf(m, logits[j]);
        float ssum = 0.f;
        #pragma unroll
        for (int j = 0; j < 10; j++) ssum += expf(logits[j] - m);
        float lse = m + logf(ssum);
        #pragma unroll
        for (int j = 0; j < 10; j++) out[gph * 10 + j] = logits[j] - lse;
    }
}

// ---------------- launch ----------------
extern "C" void kernel_launch(void* const* d_in, const int* in_sizes, int n_in,
                              void* d_out, int out_size)
{
    const float* x     = (const float*)d_in[0];
    const int*   ei    = (const int*)d_in[1];
    const int*   batch = (const int*)d_in[2];
    const float* eps   = (const float*)d_in[3];

    zero_pooled_kernel<<<512, 256>>>();

    // CSR build
    zero_deg_kernel<<<(NN + 255) / 256, 256>>>();
    hist_kernel<<<(NE + 255) / 256, 256>>>(ei);
    scan1_kernel<<<NSB, 1024>>>();
    scan2_kernel<<<1, 128>>>();
    scan3_kernel<<<NSB, 1024>>>();
    csr_scatter_kernel<<<(NE + 255) / 256, 256>>>(ei);

    // y0 = x @ W1_0
    gemm_pre_kernel<<<(NN + 31) / 32, 256>>>(x, (const float*)d_in[4], NN);

    for (int l = 0; l < 4; l++) {
        const float *b1, *gg, *be, *W2, *b2;
        if (l == 0) {
            b1 = (const float*)d_in[5];
            gg = (const float*)d_in[6]; be = (const float*)d_in[7];
            W2 = (const float*)d_in[8]; b2 = (const float*)d_in[9];
        } else {
            int j = l - 1;
            b1 = (const float*)d_in[11] + j * 64;
            gg = (const float*)d_in[12] + j * 64; be = (const float*)d_in[13] + j * 64;
            W2 = (const float*)d_in[14] + j * 64 * 64; b2 = (const float*)d_in[15] + j * 64;
        }
        const float* W1n = (l < 3) ? ((const float*)d_in[10] + l * 64 * 64) : (const float*)d_in[10];
        int has_next = (l < 3) ? 1 : 0;

        aggregate_kernel<<<(NN * 32 + 255) / 256, 256>>>(eps, l, b1);
        bn_finalize_kernel<<<1, 64>>>(gg, be, 1.0f / (float)NN);
        gemm_dual_kernel<<<(NN + 63) / 64, 256>>>(W2, b2, batch, l * 64, W1n, has_next, NN);
    }

    head1_kernel<<<NG, 64>>>((const float*)d_in[16], (const float*)d_in[17]);
    head_bn_kernel<<<64, 256>>>((const float*)d_in[18], (const float*)d_in[19]);
    head_final_kernel<<<NG, 64>>>((const float*)d_in[20], (const float*)d_in[21], (float*)d_out);
}

// round 4
// speedup vs baseline: 1.5182x; 1.0365x over previous
#include <cuda_runtime.h>
#include <cuda_bf16.h>
#include <math.h>

#define NN 100000
#define NE 1600000
#define NG 512
#define NSB 98   // scan blocks of 1024 -> covers 100352 >= NN

// ---------------- device scratch ----------------
__device__ __align__(256) __nv_bfloat162 g_yb[NN * 32];  // y in bf16x2: 128B/node = 1 L2 line
__device__ __align__(256) float g_t[NN * 64];            // t = (1+eps)y + gather(y) + b1
__device__ float g_stats[4 * 128];    // per-layer [sum(64), sumsq(64)]
__device__ float g_scale[64];         // head BN only
__device__ float g_shift[64];
__device__ float g_pooled[NG * 256];
__device__ float g_head1[NG * 64];
__device__ int   g_deg[NN];
__device__ int   g_off[NN + 1];
__device__ int   g_cursor[NN];
__device__ int   g_srcs[NE];
__device__ int   g_bsum[NSB];
__device__ int   g_boff[NSB];

// ---------------- f32x2 helpers ----------------
__device__ __forceinline__ unsigned long long f32x2_dup(float x) {
    unsigned long long r;
    asm("mov.b64 %0, {%1, %1};" : "=l"(r) : "f"(x));
    return r;
}
__device__ __forceinline__ void f32x2_fma(unsigned long long &d,
                                          unsigned long long a, unsigned long long b) {
    asm("fma.rn.f32x2 %0, %1, %2, %0;" : "+l"(d) : "l"(a), "l"(b));
}
__device__ __forceinline__ float2 f32x2_unpack(unsigned long long v) {
    float2 r;
    asm("mov.b64 {%0, %1}, %2;" : "=f"(r.x), "=f"(r.y) : "l"(v));
    return r;
}

// ---------------- fused zero kernel: pooled + stats + deg ----------------
// work items: pooled 131072 floats, stats 512 floats, deg 100000 ints
#define ZW (131072 + 512 + NN)
__global__ void zero_all_kernel() {
    int i = blockIdx.x * 256 + threadIdx.x;
    if (i < 131072) g_pooled[i] = 0.f;
    else if (i < 131072 + 512) g_stats[i - 131072] = 0.f;
    else if (i < ZW) g_deg[i - 131072 - 512] = 0;
}

// ---------------- CSR build ----------------
__global__ void hist_kernel(const int* __restrict__ ei) {
    int e = blockIdx.x * 256 + threadIdx.x;
    if (e < NE) atomicAdd(&g_deg[ei[NE + e]], 1);
}
__global__ void scan1_kernel() {                  // <<<NSB,1024>>>
    __shared__ int wsum[32];
    int tid = threadIdx.x;
    int i = blockIdx.x * 1024 + tid;
    int v = (i < NN) ? g_deg[i] : 0;
    int x = v;
    #pragma unroll
    for (int o = 1; o < 32; o <<= 1) {
        int t = __shfl_up_sync(0xffffffffu, x, o);
        if ((tid & 31) >= o) x += t;
    }
    if ((tid & 31) == 31) wsum[tid >> 5] = x;
    __syncthreads();
    if (tid < 32) {
        int y = wsum[tid];
        #pragma unroll
        for (int o = 1; o < 32; o <<= 1) {
            int t = __shfl_up_sync(0xffffffffu, y, o);
            if (tid >= o) y += t;
        }
        wsum[tid] = y;
    }
    __syncthreads();
    int base = (tid >= 32) ? wsum[(tid >> 5) - 1] : 0;
    int incl = x + base;
    if (i < NN) g_off[i] = incl - v;              // exclusive within block
    if (tid == 1023) g_bsum[blockIdx.x] = incl;
}
__global__ void scan2_kernel() {                  // <<<1,128>>>
    __shared__ int s[128];
    int tid = threadIdx.x;
    int v = (tid < NSB) ? g_bsum[tid] : 0;
    s[tid] = v; __syncthreads();
    for (int off = 1; off < 128; off <<= 1) {
        int t = (tid >= off) ? s[tid - off] : 0;
        __syncthreads();
        s[tid] += t;
        __syncthreads();
    }
    if (tid < NSB) g_boff[tid] = s[tid] - v;
}
__global__ void scan3_kernel() {                  // <<<NSB,1024>>>
    int i = blockIdx.x * 1024 + threadIdx.x;
    if (i < NN) {
        int v = g_off[i] + g_boff[blockIdx.x];
        g_off[i] = v;
        g_cursor[i] = v;
    }
    if (i == 0) g_off[NN] = NE;
}
__global__ void csr_scatter_kernel(const int* __restrict__ ei) {
    int e = blockIdx.x * 256 + threadIdx.x;
    if (e < NE) {
        int s = ei[e];
        int d = ei[NE + e];
        int p = atomicAdd(&g_cursor[d], 1);
        g_srcs[p] = s;
    }
}

// ---------------- gemm_pre: y = X @ W1_0 (F=128 -> 64, no bias), bf16 store ----------------
__global__ void __launch_bounds__(256) gemm_pre_kernel(
    const float* __restrict__ X, const float* __restrict__ W, int N)
{
    constexpr int F = 128;
    __shared__ float xs[F * 34];
    __shared__ float ws[F * 64];
    int tid = threadIdx.x;

    const float4* Wv = (const float4*)W;
    float4* wsv = (float4*)ws;
    #pragma unroll
    for (int i = tid; i < F * 16; i += 256) wsv[i] = Wv[i];

    int base = blockIdx.x * 32;
    int n = tid & 31, kq = tid >> 5;
    int row = base + n;
    const float4* Xv = (const float4*)X;
    #pragma unroll
    for (int q = kq; q < F / 4; q += 8) {
        float4 v = make_float4(0.f, 0.f, 0.f, 0.f);
        if (row < N) v = Xv[row * (F / 4) + q];
        xs[(4 * q + 0) * 34 + n] = v.x;
        xs[(4 * q + 1) * 34 + n] = v.y;
        xs[(4 * q + 2) * 34 + n] = v.z;
        xs[(4 * q + 3) * 34 + n] = v.w;
    }
    __syncthreads();

    int w4 = (tid >> 5) * 4;
    int cp = tid & 31;           // channel pair index
    int c = cp * 2;
    unsigned long long a00 = 0ull, a01 = 0ull, a10 = 0ull, a11 = 0ull;
    #pragma unroll 4
    for (int k = 0; k < F; k++) {
        unsigned long long xp01 = *(const unsigned long long*)&xs[k * 34 + w4];
        unsigned long long xp23 = *(const unsigned long long*)&xs[k * 34 + w4 + 2];
        float2 wv = *(const float2*)&ws[k * 64 + c];
        unsigned long long wx = f32x2_dup(wv.x), wy = f32x2_dup(wv.y);
        f32x2_fma(a00, xp01, wx); f32x2_fma(a01, xp01, wy);
        f32x2_fma(a10, xp23, wx); f32x2_fma(a11, xp23, wy);
    }
    float2 v00 = f32x2_unpack(a00), v01 = f32x2_unpack(a01);
    float2 v10 = f32x2_unpack(a10), v11 = f32x2_unpack(a11);
    float vals[4][2] = {{v00.x, v01.x}, {v00.y, v01.y}, {v10.x, v11.x}, {v10.y, v11.y}};
    #pragma unroll
    for (int j = 0; j < 4; j++) {
        int r = base + w4 + j;
        if (r < N)
            g_yb[r * 32 + cp] = __floats2bfloat162_rn(vals[j][0], vals[j][1]);
    }
}

// ---------------- aggregate: t[n] = (1+eps)*y[n] + sum_nb y + b1; fused BN stats ----------------
// warp per node; lane owns channel pair (bf16x2, 4B) -> each gather row = one 128B line
__global__ void __launch_bounds__(256) aggregate_kernel(
    const float* __restrict__ eps_arr, int layer, const float* __restrict__ b1)
{
    __shared__ float ss[128];
    int tid = threadIdx.x;
    if (tid < 128) ss[tid] = 0.f;
    __syncthreads();

    int warp = (blockIdx.x * 256 + tid) >> 5;
    int lane = tid & 31;
    if (warp < NN) {
        float oe = 1.0f + __ldg(&eps_arr[layer]);
        int beg = g_off[warp], end = g_off[warp + 1];
        float2 self = __bfloat1622float2(g_yb[warp * 32 + lane]);
        float2 acc = make_float2(self.x * oe, self.y * oe);
        for (int bse = beg; bse < end; bse += 32) {
            int m = end - bse; if (m > 32) m = 32;
            int idx = (lane < m) ? g_srcs[bse + lane] : 0;
            int t = 0;
            for (; t + 4 <= m; t += 4) {
                int s0 = __shfl_sync(0xffffffffu, idx, t);
                int s1 = __shfl_sync(0xffffffffu, idx, t + 1);
                int s2 = __shfl_sync(0xffffffffu, idx, t + 2);
                int s3 = __shfl_sync(0xffffffffu, idx, t + 3);
                float2 a = __bfloat1622float2(g_yb[s0 * 32 + lane]);
                float2 b = __bfloat1622float2(g_yb[s1 * 32 + lane]);
                float2 cc = __bfloat1622float2(g_yb[s2 * 32 + lane]);
                float2 d = __bfloat1622float2(g_yb[s3 * 32 + lane]);
                acc.x += (a.x + b.x) + (cc.x + d.x);
                acc.y += (a.y + b.y) + (cc.y + d.y);
            }
            for (; t < m; t++) {
                int s0 = __shfl_sync(0xffffffffu, idx, t);
                float2 a = __bfloat1622float2(g_yb[s0 * 32 + lane]);
                acc.x += a.x; acc.y += a.y;
            }
        }
        float2 bb = *(const float2*)&b1[2 * lane];
        acc.x += bb.x; acc.y += bb.y;
        *(float2*)&g_t[warp * 64 + 2 * lane] = acc;
        atomicAdd(&ss[2 * lane], acc.x);
        atomicAdd(&ss[2 * lane + 1], acc.y);
        atomicAdd(&ss[64 + 2 * lane], acc.x * acc.x);
        atomicAdd(&ss[64 + 2 * lane + 1], acc.y * acc.y);
    }
    __syncthreads();
    if (tid < 128) atomicAdd(&g_stats[layer * 128 + tid], ss[tid]);
}

// ---------------- gemm_dual: z=relu(bn(t)); H=relu(z@W2+b2); pool H; y_next=H@W1n (bf16) ----------------
__global__ void __launch_bounds__(256) gemm_dual_kernel(
    const float* __restrict__ W2, const float* __restrict__ B2,
    const int* __restrict__ batch, int pool_off,
    const float* __restrict__ W1n, int has_next, int N,
    int layer, const float* __restrict__ gg, const float* __restrict__ be, float ninv)
{
    __shared__ float xs[64 * 66];
    __shared__ float ws2s[64 * 64];
    __shared__ float ws1s[64 * 64];
    __shared__ float scs[64], shs[64];
    int tid = threadIdx.x;

    {
        const float4* Wv = (const float4*)W2;
        float4* dv = (float4*)ws2s;
        #pragma unroll
        for (int i = tid; i < 1024; i += 256) dv[i] = Wv[i];
    }
    if (has_next) {
        const float4* Wv = (const float4*)W1n;
        float4* dv = (float4*)ws1s;
        #pragma unroll
        for (int i = tid; i < 1024; i += 256) dv[i] = Wv[i];
    }
    if (tid < 64) {
        float mean = g_stats[layer * 128 + tid] * ninv;
        float var  = g_stats[layer * 128 + 64 + tid] * ninv - mean * mean;
        float s = gg[tid] * rsqrtf(var + 1e-5f);
        scs[tid] = s;
        shs[tid] = fmaf(-mean, s, be[tid]);
    }
    __syncthreads();

    int base = blockIdx.x * 64;
    int n = tid & 63, q0 = tid >> 6;
    int row = base + n;
    const float4* Tv = (const float4*)g_t;
    #pragma unroll
    for (int q = q0; q < 16; q += 4) {
        float4 v = make_float4(0.f, 0.f, 0.f, 0.f);
        if (row < N) {
            float4 t = Tv[row * 16 + q];
            int cb = q * 4;
            v.x = fmaxf(fmaf(t.x, scs[cb + 0], shs[cb + 0]), 0.f);
            v.y = fmaxf(fmaf(t.y, scs[cb + 1], shs[cb + 1]), 0.f);
            v.z = fmaxf(fmaf(t.z, scs[cb + 2], shs[cb + 2]), 0.f);
            v.w = fmaxf(fmaf(t.w, scs[cb + 3], shs[cb + 3]), 0.f);
        }
        xs[(4 * q + 0) * 66 + n] = v.x;
        xs[(4 * q + 1) * 66 + n] = v.y;
        xs[(4 * q + 2) * 66 + n] = v.z;
        xs[(4 * q + 3) * 66 + n] = v.w;
    }
    __syncthreads();

    int w8 = (tid >> 5) * 8;
    int cp = tid & 31;
    int c = cp * 2;
    float2 bb = *(const float2*)&B2[c];
    unsigned long long acc[4][2];
    #pragma unroll
    for (int p = 0; p < 4; p++) { acc[p][0] = f32x2_dup(bb.x); acc[p][1] = f32x2_dup(bb.y); }
    #pragma unroll 4
    for (int k = 0; k < 64; k++) {
        float2 wv = *(const float2*)&ws2s[k * 64 + c];
        unsigned long long wx = f32x2_dup(wv.x), wy = f32x2_dup(wv.y);
        #pragma unroll
        for (int p = 0; p < 4; p++) {
            unsigned long long xp = *(const unsigned long long*)&xs[k * 66 + w8 + 2 * p];
            f32x2_fma(acc[p][0], xp, wx);
            f32x2_fma(acc[p][1], xp, wy);
        }
    }
    float H[8][2];
    #pragma unroll
    for (int p = 0; p < 4; p++) {
        float2 u0 = f32x2_unpack(acc[p][0]);
        float2 u1 = f32x2_unpack(acc[p][1]);
        H[2 * p + 0][0] = fmaxf(u0.x, 0.f); H[2 * p + 0][1] = fmaxf(u1.x, 0.f);
        H[2 * p + 1][0] = fmaxf(u0.y, 0.f); H[2 * p + 1][1] = fmaxf(u1.y, 0.f);
    }

    // pooling (batch sorted -> run-compressed atomics)
    int rbase = base + w8;
    int bprev = -1; float p0 = 0.f, p1 = 0.f;
    #pragma unroll
    for (int j = 0; j < 8; j++) {
        int r = rbase + j;
        if (r < N) {
            int bg = batch[r];
            if (bg != bprev) {
                if (bprev >= 0)
                    atomicAdd((float2*)&g_pooled[bprev * 256 + pool_off + c], make_float2(p0, p1));
                bprev = bg; p0 = 0.f; p1 = 0.f;
            }
            p0 += H[j][0]; p1 += H[j][1];
        }
    }
    if (bprev >= 0)
        atomicAdd((float2*)&g_pooled[bprev * 256 + pool_off + c], make_float2(p0, p1));

    if (has_next) {
        #pragma unroll
        for (int p = 0; p < 4; p++) {
            *(float2*)&xs[c * 66 + w8 + 2 * p]       = make_float2(H[2 * p][0], H[2 * p + 1][0]);
            *(float2*)&xs[(c + 1) * 66 + w8 + 2 * p] = make_float2(H[2 * p][1], H[2 * p + 1][1]);
        }
        __syncwarp();
        unsigned long long acc2[4][2];
        #pragma unroll
        for (int p = 0; p < 4; p++) { acc2[p][0] = 0ull; acc2[p][1] = 0ull; }
        #pragma unroll 4
        for (int k = 0; k < 64; k++) {
            float2 wv = *(const float2*)&ws1s[k * 64 + c];
            unsigned long long wx = f32x2_dup(wv.x), wy = f32x2_dup(wv.y);
            #pragma unroll
            for (int p = 0; p < 4; p++) {
                unsigned long long xp = *(const unsigned long long*)&xs[k * 66 + w8 + 2 * p];
                f32x2_fma(acc2[p][0], xp, wx);
                f32x2_fma(acc2[p][1], xp, wy);
            }
        }
        #pragma unroll
        for (int p = 0; p < 4; p++) {
            float2 u0 = f32x2_unpack(acc2[p][0]);
            float2 u1 = f32x2_unpack(acc2[p][1]);
            int r0 = rbase + 2 * p, r1 = r0 + 1;
            if (r0 < N) g_yb[r0 * 32 + cp] = __floats2bfloat162_rn(u0.x, u1.x);
            if (r1 < N) g_yb[r1 * 32 + cp] = __floats2bfloat162_rn(u0.y, u1.y);
        }
    }
}

// ---------------- head ----------------
__global__ void head1_kernel(const float* __restrict__ W, const float* __restrict__ B)
{
    int gph = blockIdx.x, c = threadIdx.x;   // <<<512,64>>>
    __shared__ float xs[256];
    #pragma unroll
    for (int i = c; i < 256; i += 64) xs[i] = g_pooled[gph * 256 + i];
    __syncthreads();
    float a = B[c];
    #pragma unroll 4
    for (int k = 0; k < 256; k++) a = fmaf(xs[k], __ldg(&W[k * 64 + c]), a);
    g_head1[gph * 64 + c] = a;
}

__global__ void head_bn_kernel(const float* __restrict__ g, const float* __restrict__ be)
{
    int c = blockIdx.x; int t = threadIdx.x;  // <<<64,256>>>
    __shared__ float red[256];
    float v0 = g_head1[t * 64 + c];
    float v1 = g_head1[(t + 256) * 64 + c];
    red[t] = v0 + v1;
    __syncthreads();
    for (int o = 128; o > 0; o >>= 1) { if (t < o) red[t] += red[t + o]; __syncthreads(); }
    float mean = red[0] * (1.0f / 512.0f);
    __syncthreads();
    float d0 = v0 - mean, d1 = v1 - mean;
    red[t] = d0 * d0 + d1 * d1;
    __syncthreads();
    for (int o = 128; o > 0; o >>= 1) { if (t < o) red[t] += red[t + o]; __syncthreads(); }
    if (t == 0) {
        float var = red[0] * (1.0f / 512.0f);
        float s = g[c] * rsqrtf(var + 1e-5f);
        g_scale[c] = s;
        g_shift[c] = fmaf(-mean, s, be[c]);
    }
}

__global__ void head_final_kernel(const float* __restrict__ W, const float* __restrict__ B,
                                  float* __restrict__ out)
{
    int gph = blockIdx.x; int c = threadIdx.x;   // <<<512,64>>>
    __shared__ float hn[64];
    __shared__ float logits[10];
    hn[c] = fmaxf(fmaf(g_head1[gph * 64 + c], g_scale[c], g_shift[c]), 0.f);
    __syncthreads();
    if (c < 10) {
        float a = B[c];
        #pragma unroll
        for (int k = 0; k < 64; k++) a = fmaf(hn[k], W[k * 10 + c], a);
        logits[c] = a;
    }
    __syncthreads();
    if (c == 0) {
        float m = logits[0];
        #pragma unroll
        for (int j = 1; j < 10; j++) m = fmaxf(m, logits[j]);
        float ssum = 0.f;
        #pragma unroll
        for (int j = 0; j < 10; j++) ssum += expf(logits[j] - m);
        float lse = m + logf(ssum);
        #pragma unroll
        for (int j = 0; j < 10; j++) out[gph * 10 + j] = logits[j] - lse;
    }
}

// ---------------- launch ----------------
extern "C" void kernel_launch(void* const* d_in, const int* in_sizes, int n_in,
                              void* d_out, int out_size)
{
    const float* x     = (const float*)d_in[0];
    const int*   ei    = (const int*)d_in[1];
    const int*   batch = (const int*)d_in[2];
    const float* eps   = (const float*)d_in[3];

    zero_all_kernel<<<(ZW + 255) / 256, 256>>>();

    // CSR build
    hist_kernel<<<(NE + 255) / 256, 256>>>(ei);
    scan1_kernel<<<NSB, 1024>>>();
    scan2_kernel<<<1, 128>>>();
    scan3_kernel<<<NSB, 1024>>>();
    csr_scatter_kernel<<<(NE + 255) / 256, 256>>>(ei);

    // y0 = x @ W1_0 (stored bf16)
    gemm_pre_kernel<<<(NN + 31) / 32, 256>>>(x, (const float*)d_in[4], NN);

    for (int l = 0; l < 4; l++) {
        const float *b1, *gg, *be, *W2, *b2;
        if (l == 0) {
            b1 = (const float*)d_in[5];
            gg = (const float*)d_in[6]; be = (const float*)d_in[7];
            W2 = (const float*)d_in[8]; b2 = (const float*)d_in[9];
        } else {
            int j = l - 1;
            b1 = (const float*)d_in[11] + j * 64;
            gg = (const float*)d_in[12] + j * 64; be = (const float*)d_in[13] + j * 64;
            W2 = (const float*)d_in[14] + j * 64 * 64; b2 = (const float*)d_in[15] + j * 64;
        }
        const float* W1n = (l < 3) ? ((const float*)d_in[10] + l * 64 * 64) : (const float*)d_in[10];
        int has_next = (l < 3) ? 1 : 0;

        aggregate_kernel<<<(NN * 32 + 255) / 256, 256>>>(eps, l, b1);
        gemm_dual_kernel<<<(NN + 63) / 64, 256>>>(W2, b2, batch, l * 64, W1n, has_next, NN,
                                                  l, gg, be, 1.0f / (float)NN);
    }

    head1_kernel<<<NG, 64>>>((const float*)d_in[16], (const float*)d_in[17]);
    head_bn_kernel<<<64, 256>>>((const float*)d_in[18], (const float*)d_in[19]);
    head_final_kernel<<<NG, 64>>>((const float*)d_in[20], (const float*)d_in[21], (float*)d_out);
}